// round 7
// baseline (speedup 1.0000x reference)
#include <cuda_runtime.h>
#include <cuda_fp16.h>
#include <mma.h>
#include <math.h>

using namespace nvcuda;

#define NN 8192
#define EE 262144
#define DIN 256
#define HID 64
#define KSPLIT 2

// ---------------- scratch (device globals; no allocation allowed) ----------------
static __device__ float g_h1[NN * 128];
static __device__ float g_ht1[NN * 128];
static __device__ float g_h2[NN * 64];
static __device__ float g_htkg[NN * 64];
static __device__ float g_as1[NN * 2], g_ad1[NN * 2];
static __device__ float g_as2[NN], g_ad2[NN];
static __device__ float g_dinv[NN];
static __device__ float g_g1[NN * 64], g_he1[NN * 64];
static __device__ float g_g2[NN * 64], g_hekg[NN * 64];
static __device__ float g_q[NN * 64], g_k[NN * 64], g_v[NN * 64];
static __device__ __half g_qh[NN * 64], g_kh[NN * 64], g_vh[NN * 64];
static __device__ float g_attnout[NN * 64];
static __device__ float g_hattn[NN * 64];
static __device__ float g_fused[NN * 128];
static __device__ float g_t1[NN * 64];
static __device__ float g_qn[NN * 2];      // per (q,head) L2 norm of q
static __device__ float g_knm[2];          // per head max_k ||k||
static __device__ float g_dsum[NN * 2];    // per (q,head) softmax denominator
// CSR scratch (two graphs)
static __device__ int g_cnt_t[NN], g_cur_t[NN], g_off_t[NN + 1], g_srcs_t[EE];
static __device__ int g_cnt_e[NN], g_cur_e[NN], g_off_e[NN + 1], g_srcs_e[EE];

// ---------------- helpers ----------------
__device__ __forceinline__ void atomicMaxF(float* addr, float v) {
    if (v >= 0.f) atomicMax((int*)addr, __float_as_int(v));
    else          atomicMin((unsigned int*)addr, __float_as_uint(v));
}

__device__ __forceinline__ float leaky(float x) { return (x >= 0.f) ? x : 0.2f * x; }

// ---------------- CSR build ----------------
__global__ void hist_kernel(const int* __restrict__ ei, int* cnt) {
    int e = blockIdx.x * blockDim.x + threadIdx.x;
    if (e < EE) atomicAdd(&cnt[ei[EE + e]], 1);
}

__global__ __launch_bounds__(1024) void scan2_kernel(const int* __restrict__ cntA, int* __restrict__ offA,
                                                     const int* __restrict__ cntB, int* __restrict__ offB) {
    const int* cnt = blockIdx.x ? cntB : cntA;
    int* off = blockIdx.x ? offB : offA;
    __shared__ int sm[1024];
    int tid = threadIdx.x;
    int base = tid * 8;
    int local[8];
    int s = 0;
#pragma unroll
    for (int j = 0; j < 8; j++) { local[j] = s; s += cnt[base + j]; }
    sm[tid] = s;
    __syncthreads();
    for (int d = 1; d < 1024; d <<= 1) {
        int v = (tid >= d) ? sm[tid - d] : 0;
        __syncthreads();
        sm[tid] += v;
        __syncthreads();
    }
    int pre = (tid == 0) ? 0 : sm[tid - 1];
#pragma unroll
    for (int j = 0; j < 8; j++) off[base + j] = pre + local[j];
    if (tid == 1023) off[NN] = sm[1023];
}

__global__ void scatter_kernel(const int* __restrict__ ei, const int* __restrict__ off,
                               int* cur, int* __restrict__ srcs) {
    int e = blockIdx.x * blockDim.x + threadIdx.x;
    if (e >= EE) return;
    int d = ei[EE + e];
    int p = off[d] + atomicAdd(&cur[d], 1);
    srcs[p] = ei[e];
}

__global__ void dinv_kernel(const int* __restrict__ cnt, float* dinv) {
    int i = blockIdx.x * blockDim.x + threadIdx.x;
    if (i < NN) dinv[i] = rsqrtf((float)(cnt[i] + 1));
}

// ---------------- generic tiled GEMM: C = act(A[M,K] @ B[K,N] + bias); optional fp16 copy ----------------
__global__ __launch_bounds__(256) void gemm64(const float* __restrict__ A,
                                              const float* __restrict__ B,
                                              const float* __restrict__ bias,
                                              float* __restrict__ C,
                                              __half* __restrict__ Ch,
                                              int M, int N, int K, int act) {
    __shared__ float As[16][65];
    __shared__ float Bs[16][64];
    int tid = threadIdx.x;
    int tx = tid & 15, ty = tid >> 4;
    int m0 = blockIdx.y * 64, n0 = blockIdx.x * 64;
    float acc[4][4] = {};
    for (int k0 = 0; k0 < K; k0 += 16) {
        {
            int r = tid >> 2, c = (tid & 3) * 4;
            float4 av = *(const float4*)(A + (size_t)(m0 + r) * K + k0 + c);
            As[c + 0][r] = av.x; As[c + 1][r] = av.y; As[c + 2][r] = av.z; As[c + 3][r] = av.w;
        }
        {
            int r = tid >> 4, c = (tid & 15) * 4;
            float4 bv = *(const float4*)(B + (size_t)(k0 + r) * N + n0 + c);
            *(float4*)&Bs[r][c] = bv;
        }
        __syncthreads();
#pragma unroll
        for (int kk = 0; kk < 16; kk++) {
            float a[4], b[4];
#pragma unroll
            for (int i = 0; i < 4; i++) a[i] = As[kk][ty * 4 + i];
            float4 bv = *(float4*)&Bs[kk][tx * 4];
            b[0] = bv.x; b[1] = bv.y; b[2] = bv.z; b[3] = bv.w;
#pragma unroll
            for (int i = 0; i < 4; i++)
#pragma unroll
                for (int j = 0; j < 4; j++) acc[i][j] = fmaf(a[i], b[j], acc[i][j]);
        }
        __syncthreads();
    }
#pragma unroll
    for (int i = 0; i < 4; i++) {
        int m = m0 + ty * 4 + i;
#pragma unroll
        for (int j = 0; j < 4; j++) {
            int n = n0 + tx * 4 + j;
            float v = acc[i][j];
            if (bias) v += bias[n];
            if (act == 1) v = fmaxf(v, 0.f);
            else if (act == 2) v = (v > 0.f) ? v : expm1f(v);
            C[(size_t)m * N + n] = v;
            if (Ch) Ch[(size_t)m * N + n] = __float2half(v);
        }
    }
}

// ---------------- GAT ----------------
__global__ void gat_alpha_coef(const float* __restrict__ h, const float* __restrict__ att_src,
                               const float* __restrict__ att_dst, float* as_, float* ad_, int H) {
    int i = blockIdx.x * blockDim.x + threadIdx.x;
    if (i >= NN * H) return;
    int n = i / H, hh = i % H;
    const float* hp = h + (size_t)n * H * HID + hh * HID;
    const float* s = att_src + hh * HID;
    const float* d = att_dst + hh * HID;
    float ss = 0.f, dd = 0.f;
#pragma unroll 8
    for (int c = 0; c < HID; c++) { ss = fmaf(hp[c], s[c], ss); dd = fmaf(hp[c], d[c], dd); }
    as_[i] = ss; ad_[i] = dd;
}

// one warp per (dst, head): CSR gather, softmax in registers, fused bias+ELU.
__global__ void gat_aggr_csr(const int* __restrict__ off, const int* __restrict__ srcs,
                             const float* __restrict__ as_, const float* __restrict__ ad_,
                             const float* __restrict__ hfeat, const float* __restrict__ bias,
                             float* __restrict__ out, int H) {
    int w = (blockIdx.x * blockDim.x + threadIdx.x) >> 5;
    int lane = threadIdx.x & 31;
    if (w >= NN * H) return;
    int d = w / H, hh = w - d * H;
    int beg = off[d], end = off[d + 1];
    float adv = ad_[w];
    float selfx = leaky(as_[w] + adv);
    float m = selfx;
    for (int i = beg + lane; i < end; i += 32)
        m = fmaxf(m, leaky(__ldg(&as_[srcs[i] * H + hh]) + adv));
#pragma unroll
    for (int o = 16; o > 0; o >>= 1) m = fmaxf(m, __shfl_xor_sync(0xffffffffu, m, o));
    float ssum = (lane == 0) ? __expf(selfx - m) : 0.f;
    for (int i = beg + lane; i < end; i += 32)
        ssum += __expf(leaky(__ldg(&as_[srcs[i] * H + hh]) + adv) - m);
#pragma unroll
    for (int o = 16; o > 0; o >>= 1) ssum += __shfl_xor_sync(0xffffffffu, ssum, o);
    float inv = 1.0f / (ssum + 1e-16f);
    int stride = H * HID;
    int fo = hh * HID;
    float alf = __expf(selfx - m) * inv;
    float a0 = alf * hfeat[(size_t)d * stride + fo + lane];
    float a1 = alf * hfeat[(size_t)d * stride + fo + lane + 32];
    for (int i = beg; i < end; i++) {
        int s = srcs[i];
        float xx = leaky(__ldg(&as_[s * H + hh]) + adv);
        float al = __expf(xx - m) * inv;
        const float* hs = hfeat + (size_t)s * stride + fo;
        a0 = fmaf(al, hs[lane], a0);
        a1 = fmaf(al, hs[lane + 32], a1);
    }
    float v0 = a0 + bias[fo + lane];
    float v1 = a1 + bias[fo + lane + 32];
    v0 = (v0 > 0.f) ? v0 : expm1f(v0);   // ELU
    v1 = (v1 > 0.f) ? v1 : expm1f(v1);
    out[(size_t)d * stride + fo + lane] = v0;
    out[(size_t)d * stride + fo + lane + 32] = v1;
}

// ---------------- GCN: one warp per dst, CSR gather, fused bias+ReLU ----------------
__global__ void gcn_aggr_csr(const int* __restrict__ off, const int* __restrict__ srcs,
                             const float* __restrict__ hg, const float* __restrict__ dinv,
                             const float* __restrict__ bias, float* __restrict__ out) {
    int w = (blockIdx.x * blockDim.x + threadIdx.x) >> 5;
    int lane = threadIdx.x & 31;
    if (w >= NN) return;
    int d = w;
    int beg = off[d], end = off[d + 1];
    float dv = dinv[d];
    float a0 = dv * hg[(size_t)d * 64 + lane];
    float a1 = dv * hg[(size_t)d * 64 + lane + 32];
    for (int i = beg; i < end; i++) {
        int s = srcs[i];
        float ds = __ldg(&dinv[s]);
        const float* hs = hg + (size_t)s * 64;
        a0 = fmaf(ds, hs[lane], a0);
        a1 = fmaf(ds, hs[lane + 32], a1);
    }
    float v0 = fmaf(dv, a0, bias[lane]);
    float v1 = fmaf(dv, a1, bias[lane + 32]);
    out[(size_t)d * 64 + lane] = fmaxf(v0, 0.f);
    out[(size_t)d * 64 + lane + 32] = fmaxf(v1, 0.f);
}

// ---------------- attention ----------------
__global__ void norms_kernel(const float* __restrict__ Q, const float* __restrict__ K,
                             float* qn, float* knm) {
    int i = blockIdx.x * blockDim.x + threadIdx.x;
    if (i >= NN * 2) return;
    int q = i >> 1, h = i & 1;
    const float* qp = Q + (size_t)q * 64 + h * 32;
    const float* kp = K + (size_t)q * 64 + h * 32;
    float sq = 0.f, sk = 0.f;
#pragma unroll
    for (int c = 0; c < 32; c++) { sq = fmaf(qp[c], qp[c], sq); sk = fmaf(kp[c], kp[c], sk); }
    qn[i] = sqrtf(sq);
    atomicMaxF(&knm[h], sqrtf(sk));
}

// Pass 1: dsum[q*2+h] = sum_k exp(sc*(q.k - shift)) via HMMA; no S store.
__global__ __launch_bounds__(256) void qk_dsum_wmma(const __half* __restrict__ Qh,
                                                    const __half* __restrict__ Kh,
                                                    const float* __restrict__ qn,
                                                    const float* __restrict__ knm,
                                                    float* __restrict__ dsum) {
    __shared__ __align__(32) char buf[36864];
    __half* Qs = (__half*)buf;                 // [64][40]
    __half* Ks = (__half*)(buf + 5120);        // [128][40]
    float* stage = (float*)buf;                // overlay after sync: [8][32*36]
    int h = blockIdx.z;
    int q0 = blockIdx.y * 64, k0 = blockIdx.x * 128;
    int tid = threadIdx.x, wid = tid >> 5, lane = tid & 31;
    {
        int r = tid >> 2, c8 = (tid & 3) * 8;
        *(uint4*)&Qs[r * 40 + c8] = *(const uint4*)(Qh + (size_t)(q0 + r) * 64 + h * 32 + c8);
    }
#pragma unroll
    for (int i = 0; i < 2; i++) {
        int idx = tid + i * 256;
        int r = idx >> 2, c8 = (idx & 3) * 8;
        *(uint4*)&Ks[r * 40 + c8] = *(const uint4*)(Kh + (size_t)(k0 + r) * 64 + h * 32 + c8);
    }
    __syncthreads();
    int qsub = (wid >> 2) * 32, ksub = (wid & 3) * 32;
    wmma::fragment<wmma::accumulator, 16, 16, 16, float> acc[2][2];
#pragma unroll
    for (int mi = 0; mi < 2; mi++)
#pragma unroll
        for (int ni = 0; ni < 2; ni++) wmma::fill_fragment(acc[mi][ni], 0.0f);
#pragma unroll
    for (int ks = 0; ks < 2; ks++) {
        wmma::fragment<wmma::matrix_a, 16, 16, 16, __half, wmma::row_major> a[2];
        wmma::fragment<wmma::matrix_b, 16, 16, 16, __half, wmma::col_major> b[2];
#pragma unroll
        for (int mi = 0; mi < 2; mi++)
            wmma::load_matrix_sync(a[mi], &Qs[(qsub + mi * 16) * 40 + ks * 16], 40);
#pragma unroll
        for (int ni = 0; ni < 2; ni++)
            wmma::load_matrix_sync(b[ni], &Ks[(ksub + ni * 16) * 40 + ks * 16], 40);
#pragma unroll
        for (int mi = 0; mi < 2; mi++)
#pragma unroll
            for (int ni = 0; ni < 2; ni++)
                wmma::mma_sync(acc[mi][ni], a[mi], b[ni], acc[mi][ni]);
    }
    __syncthreads();
    float* wst = stage + wid * (32 * 36);
#pragma unroll
    for (int mi = 0; mi < 2; mi++)
#pragma unroll
        for (int ni = 0; ni < 2; ni++)
            wmma::store_matrix_sync(&wst[mi * 16 * 36 + ni * 16], acc[mi][ni], 36, wmma::mem_row_major);
    const float sc = 0.17677669529663687f;   // 1/sqrt(32)
    int q = q0 + qsub + lane;
    float shiftsc = qn[q * 2 + h] * knm[h] * sc;
    const float* sp = &wst[lane * 36];
    float rs = 0.f;
#pragma unroll
    for (int j = 0; j < 32; j++) rs += __expf(fmaf(sp[j], sc, -shiftsc));
    atomicAdd(&dsum[q * 2 + h], rs);
}

// Pass 2: fused — recompute S chunk, normalize, write head-averaged weights, P.V accumulate.
// Block: 32 q rows, both heads; loops k chunks of 128 over its split range.
__global__ __launch_bounds__(256) void attn_fused(const __half* __restrict__ Qh,
                                                  const __half* __restrict__ Kh,
                                                  const __half* __restrict__ Vh,
                                                  const float* __restrict__ qn,
                                                  const float* __restrict__ knm,
                                                  const float* __restrict__ dsum,
                                                  float* __restrict__ out,
                                                  float* __restrict__ avg) {
    extern __shared__ __align__(128) char buf[];
    __half* Qs   = (__half*)buf;                  // [32][80], head h at col h*40     (5120 B)
    __half* Vs   = (__half*)(buf + 5120);         // [128][80]                        (20480 B)
    __half* P    = (__half*)(buf + 25600);        // [64][136], row h*32+q            (17408 B)
    float*  stage= (float*)(buf + 43008);         // [64][132] fp32 / Ks overlay / epilogue [8][32*36] (36864 B)
    __half* Ks   = (__half*)(buf + 43008);        // overlay
    float*  invd = (float*)(buf + 79872);         // [64]
    float*  shsc = (float*)(buf + 80128);         // [64]
    const float sc = 0.17677669529663687f;

    int q0 = blockIdx.x * 32;
    int kbeg = blockIdx.y * (NN / KSPLIT);
    int tid = threadIdx.x, wid = tid >> 5, lane = tid & 31;

    {   // Q tile (both heads)
        int r = tid >> 3, c8 = (tid & 7) * 8;
        int sc8 = (c8 >= 32) ? (40 + c8 - 32) : c8;
        *(uint4*)&Qs[r * 80 + sc8] = *(const uint4*)(Qh + (size_t)(q0 + r) * 64 + c8);
    }
    if (tid < 64) {
        int h = tid >> 5, q = tid & 31;
        int idx = (q0 + q) * 2 + h;
        invd[tid] = 1.0f / dsum[idx];
        shsc[tid] = qn[idx] * knm[h] * sc;
    }

    int hh = wid >> 2, kseg = (wid & 3) * 32;
    wmma::fragment<wmma::accumulator, 16, 16, 16, float> accPV[2][2];
#pragma unroll
    for (int mi = 0; mi < 2; mi++)
#pragma unroll
        for (int ni = 0; ni < 2; ni++) wmma::fill_fragment(accPV[mi][ni], 0.0f);

    for (int kc = kbeg; kc < kbeg + NN / KSPLIT; kc += 128) {
        __syncthreads();   // prev iter readers of Vs / Ks-region done (also covers initial Qs load)
        // load K,V chunk (both heads): 128 rows x 64 halves each
#pragma unroll
        for (int i = 0; i < 2; i++) {
            int idx = tid + i * 256;
            int r = idx >> 2, c8 = (idx & 3) * 16;       // 2 uint4 per (r,c16)? -> use 4 chunks of 16
            // 128 rows * 4 chunks of 16 halves = 512 slots; idx in [0,512)
            int sc16 = (c8 >= 32) ? (40 + c8 - 32) : c8;
            *(uint4*)&Ks[r * 80 + sc16]     = *(const uint4*)(Kh + (size_t)(kc + r) * 64 + c8);
            *(uint4*)&Ks[r * 80 + sc16 + 8] = *(const uint4*)(Kh + (size_t)(kc + r) * 64 + c8 + 8);
            *(uint4*)&Vs[r * 80 + sc16]     = *(const uint4*)(Vh + (size_t)(kc + r) * 64 + c8);
            *(uint4*)&Vs[r * 80 + sc16 + 8] = *(const uint4*)(Vh + (size_t)(kc + r) * 64 + c8 + 8);
        }
        __syncthreads();
        // S wmma: warp: head hh, k sub-block kseg (32 wide), all 32 q rows
        wmma::fragment<wmma::accumulator, 16, 16, 16, float> accS[2][2];
#pragma unroll
        for (int mi = 0; mi < 2; mi++)
#pragma unroll
            for (int ni = 0; ni < 2; ni++) wmma::fill_fragment(accS[mi][ni], 0.0f);
#pragma unroll
        for (int ks = 0; ks < 2; ks++) {
            wmma::fragment<wmma::matrix_a, 16, 16, 16, __half, wmma::row_major> a[2];
            wmma::fragment<wmma::matrix_b, 16, 16, 16, __half, wmma::col_major> b[2];
#pragma unroll
            for (int mi = 0; mi < 2; mi++)
                wmma::load_matrix_sync(a[mi], &Qs[(mi * 16) * 80 + hh * 40 + ks * 16], 80);
#pragma unroll
            for (int ni = 0; ni < 2; ni++)
                wmma::load_matrix_sync(b[ni], &Ks[(kseg + ni * 16) * 80 + hh * 40 + ks * 16], 80);
#pragma unroll
            for (int mi = 0; mi < 2; mi++)
#pragma unroll
                for (int ni = 0; ni < 2; ni++)
                    wmma::mma_sync(accS[mi][ni], a[mi], b[ni], accS[mi][ni]);
        }
        __syncthreads();   // all warps done reading Ks before stage overwrite
#pragma unroll
        for (int mi = 0; mi < 2; mi++)
#pragma unroll
            for (int ni = 0; ni < 2; ni++)
                wmma::store_matrix_sync(&stage[(hh * 32 + mi * 16) * 132 + kseg + ni * 16],
                                        accS[mi][ni], 132, wmma::mem_row_major);
        __syncthreads();
        // exp + normalize + avg write + P fp16
        {
            int q = tid >> 3, c16 = (tid & 7) * 16;
            float i0 = invd[q], i1 = invd[32 + q];
            float s0f = shsc[q], s1f = shsc[32 + q];
            const float* st0 = &stage[q * 132 + c16];
            const float* st1 = &stage[(32 + q) * 132 + c16];
            __half2 p0h[8], p1h[8];
            float av16[16];
#pragma unroll
            for (int j = 0; j < 8; j++) {
                float e00 = __expf(fmaf(st0[2 * j], sc, -s0f)) * i0;
                float e01 = __expf(fmaf(st0[2 * j + 1], sc, -s0f)) * i0;
                float e10 = __expf(fmaf(st1[2 * j], sc, -s1f)) * i1;
                float e11 = __expf(fmaf(st1[2 * j + 1], sc, -s1f)) * i1;
                p0h[j] = __floats2half2_rn(e00, e01);
                p1h[j] = __floats2half2_rn(e10, e11);
                av16[2 * j] = 0.5f * (e00 + e10);
                av16[2 * j + 1] = 0.5f * (e01 + e11);
            }
            *(uint4*)&P[q * 136 + c16]            = *(uint4*)&p0h[0];
            *(uint4*)&P[q * 136 + c16 + 8]        = *(uint4*)&p0h[4];
            *(uint4*)&P[(32 + q) * 136 + c16]     = *(uint4*)&p1h[0];
            *(uint4*)&P[(32 + q) * 136 + c16 + 8] = *(uint4*)&p1h[4];
            size_t goff = (size_t)(q0 + q) * NN + kc + c16;
#pragma unroll
            for (int t = 0; t < 4; t++) __stcs((float4*)(avg + goff + t * 4), *(float4*)&av16[t * 4]);
        }
        __syncthreads();
        // P.V wmma: warp: head hh, k segment kseg (32 deep), accumulate 32x32
#pragma unroll
        for (int ks = 0; ks < 2; ks++) {
            wmma::fragment<wmma::matrix_a, 16, 16, 16, __half, wmma::row_major> a[2];
            wmma::fragment<wmma::matrix_b, 16, 16, 16, __half, wmma::row_major> b[2];
#pragma unroll
            for (int mi = 0; mi < 2; mi++)
                wmma::load_matrix_sync(a[mi], &P[(hh * 32 + mi * 16) * 136 + kseg + ks * 16], 136);
#pragma unroll
            for (int ni = 0; ni < 2; ni++)
                wmma::load_matrix_sync(b[ni], &Vs[(kseg + ks * 16) * 80 + hh * 40 + ni * 16], 80);
#pragma unroll
            for (int mi = 0; mi < 2; mi++)
#pragma unroll
                for (int ni = 0; ni < 2; ni++)
                    wmma::mma_sync(accPV[mi][ni], a[mi], b[ni], accPV[mi][ni]);
        }
    }
    __syncthreads();
    // epilogue: stage per-warp 32x36 tiles, reduce 4 k-segments per head, atomicAdd (k-split partials)
    float* wst = stage + wid * (32 * 36);
#pragma unroll
    for (int mi = 0; mi < 2; mi++)
#pragma unroll
        for (int ni = 0; ni < 2; ni++)
            wmma::store_matrix_sync(&wst[mi * 16 * 36 + ni * 16], accPV[mi][ni], 36, wmma::mem_row_major);
    __syncthreads();
#pragma unroll
    for (int j = 0; j < 8; j++) {
        int idx = tid + j * 256;              // 2048 outputs
        int h = idx >> 10, rem = idx & 1023;
        int q = rem >> 5, c = rem & 31;
        float v = 0.f;
#pragma unroll
        for (int s = 0; s < 4; s++) v += stage[(h * 4 + s) * (32 * 36) + q * 36 + c];
        atomicAdd(&out[(size_t)(q0 + q) * 64 + h * 32 + c], v);
    }
}

// ---------------- misc tail ----------------
__global__ void concat_kernel(const float* __restrict__ a, const float* __restrict__ b,
                              float* __restrict__ o) {
    int i = blockIdx.x * blockDim.x + threadIdx.x;
    if (i >= NN * 128) return;
    int n = i >> 7, c = i & 127;
    o[i] = (c < 64) ? a[n * 64 + c] : b[n * 64 + c - 64];
}

__global__ void fc2_kernel(const float* __restrict__ t, const float* __restrict__ W,
                           const float* __restrict__ b, float* __restrict__ pred) {
    int w = (blockIdx.x * blockDim.x + threadIdx.x) >> 5;
    int lane = threadIdx.x & 31;
    if (w >= NN) return;
    float s = t[(size_t)w * 64 + lane] * W[lane] + t[(size_t)w * 64 + lane + 32] * W[lane + 32];
#pragma unroll
    for (int off = 16; off > 0; off >>= 1) s += __shfl_down_sync(0xffffffffu, s, off);
    if (lane == 0) pred[w] = s + b[0];
}

// ---------------- launch ----------------
extern "C" void kernel_launch(void* const* d_in, const int* in_sizes, int n_in,
                              void* d_out, int out_size) {
    const float* x       = (const float*)d_in[0];
    const int*   eit     = (const int*)d_in[1];
    const int*   eie     = (const int*)d_in[2];
    const float* gat1_W  = (const float*)d_in[3];
    const float* gat1_as = (const float*)d_in[4];
    const float* gat1_ad = (const float*)d_in[5];
    const float* gat1_b  = (const float*)d_in[6];
    const float* gat2_W  = (const float*)d_in[7];
    const float* gat2_as = (const float*)d_in[8];
    const float* gat2_ad = (const float*)d_in[9];
    const float* gat2_b  = (const float*)d_in[10];
    const float* gcn1_W  = (const float*)d_in[11];
    const float* gcn1_b  = (const float*)d_in[12];
    const float* gcn2_W  = (const float*)d_in[13];
    const float* gcn2_b  = (const float*)d_in[14];
    const float* Wq = (const float*)d_in[15]; const float* bq = (const float*)d_in[16];
    const float* Wk = (const float*)d_in[17]; const float* bk = (const float*)d_in[18];
    const float* Wv = (const float*)d_in[19]; const float* bv = (const float*)d_in[20];
    const float* Wo = (const float*)d_in[21]; const float* bo = (const float*)d_in[22];
    const float* fc1_W = (const float*)d_in[23]; const float* fc1_b = (const float*)d_in[24];
    const float* fc2_W = (const float*)d_in[25]; const float* fc2_b = (const float*)d_in[26];

    float* out_pred = (float*)d_out;
    float* out_attn = (float*)d_out + NN;

    __half *pqh, *pkh, *pvh;
    float *ph1, *pht1, *ph2, *phtkg, *pas1, *pad1, *pas2, *pad2;
    float *pdinv, *pg1, *phe1, *pg2, *phekg;
    float *pq, *pk, *pv, *pao, *phat, *pfus, *pt1, *pqn, *pknm, *pdsum;
    int *pcnt_t, *pcur_t, *poff_t, *psrcs_t, *pcnt_e, *pcur_e, *poff_e, *psrcs_e;
    cudaGetSymbolAddress((void**)&pqh, g_qh);    cudaGetSymbolAddress((void**)&pkh, g_kh);
    cudaGetSymbolAddress((void**)&pvh, g_vh);
    cudaGetSymbolAddress((void**)&ph1, g_h1);    cudaGetSymbolAddress((void**)&pht1, g_ht1);
    cudaGetSymbolAddress((void**)&ph2, g_h2);    cudaGetSymbolAddress((void**)&phtkg, g_htkg);
    cudaGetSymbolAddress((void**)&pas1, g_as1);  cudaGetSymbolAddress((void**)&pad1, g_ad1);
    cudaGetSymbolAddress((void**)&pas2, g_as2);  cudaGetSymbolAddress((void**)&pad2, g_ad2);
    cudaGetSymbolAddress((void**)&pdinv, g_dinv);
    cudaGetSymbolAddress((void**)&pg1, g_g1);    cudaGetSymbolAddress((void**)&phe1, g_he1);
    cudaGetSymbolAddress((void**)&pg2, g_g2);    cudaGetSymbolAddress((void**)&phekg, g_hekg);
    cudaGetSymbolAddress((void**)&pq, g_q);      cudaGetSymbolAddress((void**)&pk, g_k);
    cudaGetSymbolAddress((void**)&pv, g_v);      cudaGetSymbolAddress((void**)&pao, g_attnout);
    cudaGetSymbolAddress((void**)&phat, g_hattn);cudaGetSymbolAddress((void**)&pfus, g_fused);
    cudaGetSymbolAddress((void**)&pt1, g_t1);
    cudaGetSymbolAddress((void**)&pqn, g_qn);    cudaGetSymbolAddress((void**)&pknm, g_knm);
    cudaGetSymbolAddress((void**)&pdsum, g_dsum);
    cudaGetSymbolAddress((void**)&pcnt_t, g_cnt_t); cudaGetSymbolAddress((void**)&pcur_t, g_cur_t);
    cudaGetSymbolAddress((void**)&poff_t, g_off_t); cudaGetSymbolAddress((void**)&psrcs_t, g_srcs_t);
    cudaGetSymbolAddress((void**)&pcnt_e, g_cnt_e); cudaGetSymbolAddress((void**)&pcur_e, g_cur_e);
    cudaGetSymbolAddress((void**)&poff_e, g_off_e); cudaGetSymbolAddress((void**)&psrcs_e, g_srcs_e);

    static int smem_set = 0;
    const int ATTN_SMEM = 80384;
    if (!smem_set) {
        cudaFuncSetAttribute(attn_fused, cudaFuncAttributeMaxDynamicSharedMemorySize, ATTN_SMEM);
        smem_set = 1;
    }

    const int T = 256;
    const int EB = (EE + T - 1) / T;

    // ===== CSR build (both graphs) =====
    cudaMemsetAsync(pcnt_t, 0, NN * sizeof(int));
    cudaMemsetAsync(pcur_t, 0, NN * sizeof(int));
    cudaMemsetAsync(pcnt_e, 0, NN * sizeof(int));
    cudaMemsetAsync(pcur_e, 0, NN * sizeof(int));
    hist_kernel<<<EB, T>>>(eit, pcnt_t);
    hist_kernel<<<EB, T>>>(eie, pcnt_e);
    scan2_kernel<<<2, 1024>>>(pcnt_t, poff_t, pcnt_e, poff_e);
    scatter_kernel<<<EB, T>>>(eit, poff_t, pcur_t, psrcs_t);
    scatter_kernel<<<EB, T>>>(eie, poff_e, pcur_e, psrcs_e);
    dinv_kernel<<<(NN + T - 1) / T, T>>>(pcnt_e, pdinv);

    // ===== GAT layer 1 (heads=2, concat) =====
    gemm64<<<dim3(2, 128), 256>>>(x, gat1_W, nullptr, ph1, nullptr, NN, 128, DIN, 0);
    gat_alpha_coef<<<(NN * 2 + T - 1) / T, T>>>(ph1, gat1_as, gat1_ad, pas1, pad1, 2);
    gat_aggr_csr<<<(NN * 2 * 32 + T - 1) / T, T>>>(poff_t, psrcs_t, pas1, pad1, ph1, gat1_b, pht1, 2);

    // ===== GAT layer 2 (heads=1) =====
    gemm64<<<dim3(1, 128), 256>>>(pht1, gat2_W, nullptr, ph2, nullptr, NN, 64, 128, 0);
    gat_alpha_coef<<<(NN + T - 1) / T, T>>>(ph2, gat2_as, gat2_ad, pas2, pad2, 1);
    gat_aggr_csr<<<(NN * 32 + T - 1) / T, T>>>(poff_t, psrcs_t, pas2, pad2, ph2, gat2_b, phtkg, 1);

    // ===== GCN branch =====
    gemm64<<<dim3(1, 128), 256>>>(x, gcn1_W, nullptr, pg1, nullptr, NN, 64, DIN, 0);
    gcn_aggr_csr<<<(NN * 32 + T - 1) / T, T>>>(poff_e, psrcs_e, pg1, pdinv, gcn1_b, phe1);
    gemm64<<<dim3(1, 128), 256>>>(phe1, gcn2_W, nullptr, pg2, nullptr, NN, 64, 64, 0);
    gcn_aggr_csr<<<(NN * 32 + T - 1) / T, T>>>(poff_e, psrcs_e, pg2, pdinv, gcn2_b, phekg);

    // ===== cross attention (2-pass fused; no S materialization) =====
    gemm64<<<dim3(1, 128), 256>>>(phtkg, Wq, bq, pq, pqh, NN, 64, 64, 0);
    gemm64<<<dim3(1, 128), 256>>>(phekg, Wk, bk, pk, pkh, NN, 64, 64, 0);
    gemm64<<<dim3(1, 128), 256>>>(phekg, Wv, bv, pv, pvh, NN, 64, 64, 0);
    cudaMemsetAsync(pknm, 0, 2 * sizeof(float));
    cudaMemsetAsync(pdsum, 0, NN * 2 * sizeof(float));
    norms_kernel<<<(NN * 2 + T - 1) / T, T>>>(pq, pk, pqn, pknm);
    qk_dsum_wmma<<<dim3(64, 128, 2), 256>>>(pqh, pkh, pqn, pknm, pdsum);
    cudaMemsetAsync(pao, 0, (size_t)NN * 64 * sizeof(float));
    attn_fused<<<dim3(NN / 32, KSPLIT), 256, ATTN_SMEM>>>(pqh, pkh, pvh, pqn, pknm, pdsum, pao, out_attn);
    gemm64<<<dim3(1, 128), 256>>>(pao, Wo, bo, phat, nullptr, NN, 64, 64, 0);

    // ===== head =====
    concat_kernel<<<(NN * 128 + T - 1) / T, T>>>(phtkg, phat, pfus);
    gemm64<<<dim3(1, 128), 256>>>(pfus, fc1_W, fc1_b, pt1, nullptr, NN, 64, 128, 1);
    fc2_kernel<<<(NN * 32 + T - 1) / T, T>>>(pt1, fc2_W, fc2_b, out_pred);
}

// round 8
// speedup vs baseline: 1.1960x; 1.1960x over previous
#include <cuda_runtime.h>
#include <cuda_fp16.h>
#include <mma.h>
#include <math.h>

using namespace nvcuda;

#define NN 8192
#define EE 262144
#define DIN 256
#define HID 64

// ---------------- scratch (device globals; no allocation allowed) ----------------
static __device__ __half g_S[(size_t)2 * NN * NN];         // 268 MB: per-head unnormalized exp scores (fp16)
static __device__ float g_h1[NN * 128];
static __device__ float g_ht1[NN * 128];
static __device__ float g_h2[NN * 64];
static __device__ float g_htkg[NN * 64];
static __device__ float g_as1[NN * 2], g_ad1[NN * 2];
static __device__ float g_as2[NN], g_ad2[NN];
static __device__ float g_dinv[NN];
static __device__ float g_g1[NN * 64], g_he1[NN * 64];
static __device__ float g_g2[NN * 64], g_hekg[NN * 64];
static __device__ float g_q[NN * 64], g_k[NN * 64], g_v[NN * 64];
static __device__ __half g_qh[NN * 64], g_kh[NN * 64], g_vh[NN * 64];
static __device__ float g_attnout[NN * 64];
static __device__ float g_hattn[NN * 64];
static __device__ float g_t1[NN * 64];
static __device__ float g_qn[NN * 2];      // per (q,head) L2 norm of q
static __device__ float g_knm[2];          // per head max_k ||k||
static __device__ float g_dsum[NN * 2];    // per (q,head) softmax denominator
// CSR scratch (two graphs)
static __device__ int g_cnt_t[NN], g_cur_t[NN], g_off_t[NN + 1], g_srcs_t[EE];
static __device__ int g_cnt_e[NN], g_cur_e[NN], g_off_e[NN + 1], g_srcs_e[EE];

// ---------------- helpers ----------------
__device__ __forceinline__ void atomicMaxF(float* addr, float v) {
    if (v >= 0.f) atomicMax((int*)addr, __float_as_int(v));
    else          atomicMin((unsigned int*)addr, __float_as_uint(v));
}

__device__ __forceinline__ float leaky(float x) { return (x >= 0.f) ? x : 0.2f * x; }

// ---------------- CSR build ----------------
__global__ void hist_kernel(const int* __restrict__ ei, int* cnt) {
    int e = blockIdx.x * blockDim.x + threadIdx.x;
    if (e < EE) atomicAdd(&cnt[ei[EE + e]], 1);
}

__global__ __launch_bounds__(1024) void scan_kernel(const int* __restrict__ cnt, int* __restrict__ off) {
    __shared__ int sm[1024];
    int tid = threadIdx.x;
    int base = tid * 8;
    int local[8];
    int s = 0;
#pragma unroll
    for (int j = 0; j < 8; j++) { local[j] = s; s += cnt[base + j]; }
    sm[tid] = s;
    __syncthreads();
    for (int d = 1; d < 1024; d <<= 1) {
        int v = (tid >= d) ? sm[tid - d] : 0;
        __syncthreads();
        sm[tid] += v;
        __syncthreads();
    }
    int pre = (tid == 0) ? 0 : sm[tid - 1];
#pragma unroll
    for (int j = 0; j < 8; j++) off[base + j] = pre + local[j];
    if (tid == 1023) off[NN] = sm[1023];
}

__global__ void scatter_kernel(const int* __restrict__ ei, const int* __restrict__ off,
                               int* cur, int* __restrict__ srcs) {
    int e = blockIdx.x * blockDim.x + threadIdx.x;
    if (e >= EE) return;
    int d = ei[EE + e];
    int p = off[d] + atomicAdd(&cur[d], 1);
    srcs[p] = ei[e];
}

__global__ void dinv_kernel(const int* __restrict__ cnt, float* dinv) {
    int i = blockIdx.x * blockDim.x + threadIdx.x;
    if (i < NN) dinv[i] = rsqrtf((float)(cnt[i] + 1));
}

// ---------------- generic tiled GEMM: C = act(A[M,K] @ B[K,N] + bias) ----------------
// If A2 != null: logical A = [A | A2], each half K/2 wide with row stride K/2 (fused concat).
// Optional fp16 copy of C into Ch.
__global__ __launch_bounds__(256) void gemm64(const float* __restrict__ A,
                                              const float* __restrict__ A2,
                                              const float* __restrict__ B,
                                              const float* __restrict__ bias,
                                              float* __restrict__ C,
                                              __half* __restrict__ Ch,
                                              int M, int N, int K, int act) {
    __shared__ float As[16][65];
    __shared__ float Bs[16][64];
    int tid = threadIdx.x;
    int tx = tid & 15, ty = tid >> 4;
    int m0 = blockIdx.y * 64, n0 = blockIdx.x * 64;
    float acc[4][4] = {};
    for (int k0 = 0; k0 < K; k0 += 16) {
        {
            int r = tid >> 2, c = (tid & 3) * 4;
            const float* src;
            if (A2 == nullptr) {
                src = A + (size_t)(m0 + r) * K + k0 + c;
            } else {
                int kk = k0 + c, half = K >> 1;
                src = (kk < half) ? (A  + (size_t)(m0 + r) * half + kk)
                                  : (A2 + (size_t)(m0 + r) * half + kk - half);
            }
            float4 av = *(const float4*)src;
            As[c + 0][r] = av.x; As[c + 1][r] = av.y; As[c + 2][r] = av.z; As[c + 3][r] = av.w;
        }
        {
            int r = tid >> 4, c = (tid & 15) * 4;
            float4 bv = *(const float4*)(B + (size_t)(k0 + r) * N + n0 + c);
            *(float4*)&Bs[r][c] = bv;
        }
        __syncthreads();
#pragma unroll
        for (int kk = 0; kk < 16; kk++) {
            float a[4], b[4];
#pragma unroll
            for (int i = 0; i < 4; i++) a[i] = As[kk][ty * 4 + i];
            float4 bv = *(float4*)&Bs[kk][tx * 4];
            b[0] = bv.x; b[1] = bv.y; b[2] = bv.z; b[3] = bv.w;
#pragma unroll
            for (int i = 0; i < 4; i++)
#pragma unroll
                for (int j = 0; j < 4; j++) acc[i][j] = fmaf(a[i], b[j], acc[i][j]);
        }
        __syncthreads();
    }
#pragma unroll
    for (int i = 0; i < 4; i++) {
        int m = m0 + ty * 4 + i;
#pragma unroll
        for (int j = 0; j < 4; j++) {
            int n = n0 + tx * 4 + j;
            float v = acc[i][j];
            if (bias) v += bias[n];
            if (act == 1) v = fmaxf(v, 0.f);
            else if (act == 2) v = (v > 0.f) ? v : expm1f(v);
            C[(size_t)m * N + n] = v;
            if (Ch) Ch[(size_t)m * N + n] = __float2half(v);
        }
    }
}

// ---------------- GAT ----------------
__global__ void gat_alpha_coef(const float* __restrict__ h, const float* __restrict__ att_src,
                               const float* __restrict__ att_dst, float* as_, float* ad_, int H) {
    int i = blockIdx.x * blockDim.x + threadIdx.x;
    if (i >= NN * H) return;
    int n = i / H, hh = i % H;
    const float* hp = h + (size_t)n * H * HID + hh * HID;
    const float* s = att_src + hh * HID;
    const float* d = att_dst + hh * HID;
    float ss = 0.f, dd = 0.f;
#pragma unroll 8
    for (int c = 0; c < HID; c++) { ss = fmaf(hp[c], s[c], ss); dd = fmaf(hp[c], d[c], dd); }
    as_[i] = ss; ad_[i] = dd;
}

// one warp per (dst, head): CSR gather, softmax in registers, fused bias+ELU.
__global__ void gat_aggr_csr(const int* __restrict__ off, const int* __restrict__ srcs,
                             const float* __restrict__ as_, const float* __restrict__ ad_,
                             const float* __restrict__ hfeat, const float* __restrict__ bias,
                             float* __restrict__ out, int H) {
    int w = (blockIdx.x * blockDim.x + threadIdx.x) >> 5;
    int lane = threadIdx.x & 31;
    if (w >= NN * H) return;
    int d = w / H, hh = w - d * H;
    int beg = off[d], end = off[d + 1];
    float adv = ad_[w];
    float selfx = leaky(as_[w] + adv);
    float m = selfx;
    for (int i = beg + lane; i < end; i += 32)
        m = fmaxf(m, leaky(__ldg(&as_[srcs[i] * H + hh]) + adv));
#pragma unroll
    for (int o = 16; o > 0; o >>= 1) m = fmaxf(m, __shfl_xor_sync(0xffffffffu, m, o));
    float ssum = (lane == 0) ? __expf(selfx - m) : 0.f;
    for (int i = beg + lane; i < end; i += 32)
        ssum += __expf(leaky(__ldg(&as_[srcs[i] * H + hh]) + adv) - m);
#pragma unroll
    for (int o = 16; o > 0; o >>= 1) ssum += __shfl_xor_sync(0xffffffffu, ssum, o);
    float inv = 1.0f / (ssum + 1e-16f);
    int stride = H * HID;
    int fo = hh * HID;
    float alf = __expf(selfx - m) * inv;
    float a0 = alf * hfeat[(size_t)d * stride + fo + lane];
    float a1 = alf * hfeat[(size_t)d * stride + fo + lane + 32];
    for (int i = beg; i < end; i++) {
        int s = srcs[i];
        float xx = leaky(__ldg(&as_[s * H + hh]) + adv);
        float al = __expf(xx - m) * inv;
        const float* hs = hfeat + (size_t)s * stride + fo;
        a0 = fmaf(al, hs[lane], a0);
        a1 = fmaf(al, hs[lane + 32], a1);
    }
    float v0 = a0 + bias[fo + lane];
    float v1 = a1 + bias[fo + lane + 32];
    v0 = (v0 > 0.f) ? v0 : expm1f(v0);   // ELU
    v1 = (v1 > 0.f) ? v1 : expm1f(v1);
    out[(size_t)d * stride + fo + lane] = v0;
    out[(size_t)d * stride + fo + lane + 32] = v1;
}

// ---------------- GCN: one warp per dst, CSR gather, fused bias+ReLU ----------------
__global__ void gcn_aggr_csr(const int* __restrict__ off, const int* __restrict__ srcs,
                             const float* __restrict__ hg, const float* __restrict__ dinv,
                             const float* __restrict__ bias, float* __restrict__ out) {
    int w = (blockIdx.x * blockDim.x + threadIdx.x) >> 5;
    int lane = threadIdx.x & 31;
    if (w >= NN) return;
    int d = w;
    int beg = off[d], end = off[d + 1];
    float dv = dinv[d];
    float a0 = dv * hg[(size_t)d * 64 + lane];
    float a1 = dv * hg[(size_t)d * 64 + lane + 32];
    for (int i = beg; i < end; i++) {
        int s = srcs[i];
        float ds = __ldg(&dinv[s]);
        const float* hs = hg + (size_t)s * 64;
        a0 = fmaf(ds, hs[lane], a0);
        a1 = fmaf(ds, hs[lane + 32], a1);
    }
    float v0 = fmaf(dv, a0, bias[lane]);
    float v1 = fmaf(dv, a1, bias[lane + 32]);
    out[(size_t)d * 64 + lane] = fmaxf(v0, 0.f);
    out[(size_t)d * 64 + lane + 32] = fmaxf(v1, 0.f);
}

// ---------------- attention ----------------
__global__ void norms_kernel(const float* __restrict__ Q, const float* __restrict__ K,
                             float* qn, float* knm) {
    int i = blockIdx.x * blockDim.x + threadIdx.x;
    if (i >= NN * 2) return;
    int q = i >> 1, h = i & 1;
    const float* qp = Q + (size_t)q * 64 + h * 32;
    const float* kp = K + (size_t)q * 64 + h * 32;
    float sq = 0.f, sk = 0.f;
#pragma unroll
    for (int c = 0; c < 32; c++) { sq = fmaf(qp[c], qp[c], sq); sk = fmaf(kp[c], kp[c], sk); }
    qn[i] = sqrtf(sq);
    atomicMaxF(&knm[h], sqrtf(sk));
}

// E[h][q][k] = exp(scale*(q.k - ||q||*knm)) via HMMA; fp16 store; fp32 row sums -> dsum.
__global__ __launch_bounds__(256) void qk_exp_wmma(const __half* __restrict__ Qh,
                                                   const __half* __restrict__ Kh,
                                                   const float* __restrict__ qn,
                                                   const float* __restrict__ knm,
                                                   __half* __restrict__ S,
                                                   float* __restrict__ dsum) {
    __shared__ __align__(32) char buf[36864];
    __half* Qs = (__half*)buf;                 // [64][40]
    __half* Ks = (__half*)(buf + 5120);        // [128][40]
    float* stage = (float*)buf;                // overlay after sync: [8][32*36]
    int h = blockIdx.z;
    int q0 = blockIdx.y * 64, k0 = blockIdx.x * 128;
    int tid = threadIdx.x, wid = tid >> 5, lane = tid & 31;
    {
        int r = tid >> 2, c8 = (tid & 3) * 8;
        *(uint4*)&Qs[r * 40 + c8] = *(const uint4*)(Qh + (size_t)(q0 + r) * 64 + h * 32 + c8);
    }
#pragma unroll
    for (int i = 0; i < 2; i++) {
        int idx = tid + i * 256;
        int r = idx >> 2, c8 = (idx & 3) * 8;
        *(uint4*)&Ks[r * 40 + c8] = *(const uint4*)(Kh + (size_t)(k0 + r) * 64 + h * 32 + c8);
    }
    __syncthreads();
    int qsub = (wid >> 2) * 32, ksub = (wid & 3) * 32;
    wmma::fragment<wmma::accumulator, 16, 16, 16, float> acc[2][2];
#pragma unroll
    for (int mi = 0; mi < 2; mi++)
#pragma unroll
        for (int ni = 0; ni < 2; ni++) wmma::fill_fragment(acc[mi][ni], 0.0f);
#pragma unroll
    for (int ks = 0; ks < 2; ks++) {
        wmma::fragment<wmma::matrix_a, 16, 16, 16, __half, wmma::row_major> a[2];
        wmma::fragment<wmma::matrix_b, 16, 16, 16, __half, wmma::col_major> b[2];
#pragma unroll
        for (int mi = 0; mi < 2; mi++)
            wmma::load_matrix_sync(a[mi], &Qs[(qsub + mi * 16) * 40 + ks * 16], 40);
#pragma unroll
        for (int ni = 0; ni < 2; ni++)
            wmma::load_matrix_sync(b[ni], &Ks[(ksub + ni * 16) * 40 + ks * 16], 40);
#pragma unroll
        for (int mi = 0; mi < 2; mi++)
#pragma unroll
            for (int ni = 0; ni < 2; ni++)
                wmma::mma_sync(acc[mi][ni], a[mi], b[ni], acc[mi][ni]);
    }
    __syncthreads();
    float* wst = stage + wid * (32 * 36);
#pragma unroll
    for (int mi = 0; mi < 2; mi++)
#pragma unroll
        for (int ni = 0; ni < 2; ni++)
            wmma::store_matrix_sync(&wst[mi * 16 * 36 + ni * 16], acc[mi][ni], 36, wmma::mem_row_major);
    const float sc = 0.17677669529663687f;   // 1/sqrt(32)
    int q = q0 + qsub + lane;
    float shiftsc = qn[q * 2 + h] * knm[h] * sc;
    const float* sp = &wst[lane * 36];
    float rs = 0.f;
    __half2 hv[16];
#pragma unroll
    for (int j = 0; j < 16; j++) {
        float e0 = __expf(fmaf(sp[2 * j], sc, -shiftsc));
        float e1 = __expf(fmaf(sp[2 * j + 1], sc, -shiftsc));
        hv[j] = __floats2half2_rn(e0, e1);
        rs += e0 + e1;
    }
    __half* Sp = S + (size_t)h * NN * NN + (size_t)q * NN + k0 + ksub;
#pragma unroll
    for (int t = 0; t < 4; t++) __stcs((uint4*)(Sp + t * 8), *(uint4*)&hv[t * 4]);
    atomicAdd(&dsum[q * 2 + h], rs);
}

// out[q, h*32+c] += sum_k (E/dsum) * V; streams head-averaged normalized weights.
__global__ __launch_bounds__(256) void av_wmma(const __half* __restrict__ Sh,
                                               const __half* __restrict__ Vh,
                                               const float* __restrict__ dsum,
                                               float* __restrict__ out,
                                               float* __restrict__ avg) {
    __shared__ __align__(32) char buf[36864];
    __half* E0s = (__half*)buf;                // [128][40]
    __half* E1s = (__half*)(buf + 10240);      // [128][40]
    __half* Vs  = (__half*)(buf + 20480);      // [32][72]
    float* stage = (float*)buf;                // overlay at end: [8][32*36]
    __shared__ float invd[256];
    int q0 = blockIdx.x * 128;
    int kbase = blockIdx.y * 2048;
    int tid = threadIdx.x, wid = tid >> 5, lane = tid & 31;
    if (tid < 128) invd[tid] = 1.0f / dsum[(q0 + tid) * 2];
    else           invd[tid] = 1.0f / dsum[(q0 + tid - 128) * 2 + 1];
    int hh = wid >> 2, qsub = (wid & 3) * 32;
    wmma::fragment<wmma::accumulator, 16, 16, 16, float> acc[2][2];
#pragma unroll
    for (int mi = 0; mi < 2; mi++)
#pragma unroll
        for (int ni = 0; ni < 2; ni++) wmma::fill_fragment(acc[mi][ni], 0.0f);
    for (int kc = 0; kc < 2048; kc += 32) {
        __syncthreads();
#pragma unroll
        for (int i = 0; i < 2; i++) {
            int idx = tid + i * 256;
            int r = idx >> 2, c8 = (idx & 3) * 8;
            size_t goff = (size_t)(q0 + r) * NN + kbase + kc + c8;
            uint4 u0 = __ldcs((const uint4*)(Sh + goff));
            uint4 u1 = __ldcs((const uint4*)(Sh + (size_t)NN * NN + goff));
            *(uint4*)&E0s[r * 40 + c8] = u0;
            *(uint4*)&E1s[r * 40 + c8] = u1;
            float i0 = invd[r], i1 = invd[128 + r];
            __half2* a0 = (__half2*)&u0;
            __half2* a1 = (__half2*)&u1;
            float av8[8];
#pragma unroll
            for (int j = 0; j < 4; j++) {
                float2 f0 = __half22float2(a0[j]);
                float2 f1 = __half22float2(a1[j]);
                av8[2 * j]     = 0.5f * (f0.x * i0 + f1.x * i1);
                av8[2 * j + 1] = 0.5f * (f0.y * i0 + f1.y * i1);
            }
            __stcs((float4*)(avg + goff), *(float4*)&av8[0]);
            __stcs((float4*)(avg + goff + 4), *(float4*)&av8[4]);
        }
        {
            int r = tid >> 3, c8 = (tid & 7) * 8;
            *(uint4*)&Vs[r * 72 + c8] = *(const uint4*)(Vh + (size_t)(kbase + kc + r) * 64 + c8);
        }
        __syncthreads();
        // normalize E in smem happened at load; scale to P implicitly via invd above
        __half* Es = hh ? E1s : E0s;
        // NOTE: E stored unnormalized fp16; multiply after MMA is wrong per-row — so we
        // normalized during load? No: E0s holds raw fp16. Normalize via fragment would be
        // wrong. Instead we rely on loading normalized values: rescale here.
#pragma unroll
        for (int ks = 0; ks < 2; ks++) {
            wmma::fragment<wmma::matrix_a, 16, 16, 16, __half, wmma::row_major> a[2];
            wmma::fragment<wmma::matrix_b, 16, 16, 16, __half, wmma::row_major> b[2];
#pragma unroll
            for (int mi = 0; mi < 2; mi++)
                wmma::load_matrix_sync(a[mi], &Es[(qsub + mi * 16) * 40 + ks * 16], 40);
#pragma unroll
            for (int ni = 0; ni < 2; ni++)
                wmma::load_matrix_sync(b[ni], &Vs[(ks * 16) * 72 + hh * 32 + ni * 16], 72);
#pragma unroll
            for (int mi = 0; mi < 2; mi++)
#pragma unroll
                for (int ni = 0; ni < 2; ni++)
                    wmma::mma_sync(acc[mi][ni], a[mi], b[ni], acc[mi][ni]);
        }
    }
    __syncthreads();
    float* wst = stage + wid * (32 * 36);
#pragma unroll
    for (int mi = 0; mi < 2; mi++)
#pragma unroll
        for (int ni = 0; ni < 2; ni++)
            wmma::store_matrix_sync(&wst[mi * 16 * 36 + ni * 16], acc[mi][ni], 36, wmma::mem_row_major);
    int q = q0 + qsub + lane;
    float invq = 1.0f / dsum[q * 2 + hh];
    const float* sp = &wst[lane * 36];
#pragma unroll
    for (int j = 0; j < 32; j++)
        atomicAdd(&out[(size_t)q * 64 + hh * 32 + j], sp[j] * invq);
}

// ---------------- misc tail ----------------
__global__ void fc2_kernel(const float* __restrict__ t, const float* __restrict__ W,
                           const float* __restrict__ b, float* __restrict__ pred) {
    int w = (blockIdx.x * blockDim.x + threadIdx.x) >> 5;
    int lane = threadIdx.x & 31;
    if (w >= NN) return;
    float s = t[(size_t)w * 64 + lane] * W[lane] + t[(size_t)w * 64 + lane + 32] * W[lane + 32];
#pragma unroll
    for (int off = 16; off > 0; off >>= 1) s += __shfl_down_sync(0xffffffffu, s, off);
    if (lane == 0) pred[w] = s + b[0];
}

// ---------------- launch ----------------
extern "C" void kernel_launch(void* const* d_in, const int* in_sizes, int n_in,
                              void* d_out, int out_size) {
    const float* x       = (const float*)d_in[0];
    const int*   eit     = (const int*)d_in[1];
    const int*   eie     = (const int*)d_in[2];
    const float* gat1_W  = (const float*)d_in[3];
    const float* gat1_as = (const float*)d_in[4];
    const float* gat1_ad = (const float*)d_in[5];
    const float* gat1_b  = (const float*)d_in[6];
    const float* gat2_W  = (const float*)d_in[7];
    const float* gat2_as = (const float*)d_in[8];
    const float* gat2_ad = (const float*)d_in[9];
    const float* gat2_b  = (const float*)d_in[10];
    const float* gcn1_W  = (const float*)d_in[11];
    const float* gcn1_b  = (const float*)d_in[12];
    const float* gcn2_W  = (const float*)d_in[13];
    const float* gcn2_b  = (const float*)d_in[14];
    const float* Wq = (const float*)d_in[15]; const float* bq = (const float*)d_in[16];
    const float* Wk = (const float*)d_in[17]; const float* bk = (const float*)d_in[18];
    const float* Wv = (const float*)d_in[19]; const float* bv = (const float*)d_in[20];
    const float* Wo = (const float*)d_in[21]; const float* bo = (const float*)d_in[22];
    const float* fc1_W = (const float*)d_in[23]; const float* fc1_b = (const float*)d_in[24];
    const float* fc2_W = (const float*)d_in[25]; const float* fc2_b = (const float*)d_in[26];

    float* out_pred = (float*)d_out;
    float* out_attn = (float*)d_out + NN;

    __half *pS, *pqh, *pkh, *pvh;
    float *ph1, *pht1, *ph2, *phtkg, *pas1, *pad1, *pas2, *pad2;
    float *pdinv, *pg1, *phe1, *pg2, *phekg;
    float *pq, *pk, *pv, *pao, *phat, *pt1, *pqn, *pknm, *pdsum;
    int *pcnt_t, *pcur_t, *poff_t, *psrcs_t, *pcnt_e, *pcur_e, *poff_e, *psrcs_e;
    cudaGetSymbolAddress((void**)&pS, g_S);
    cudaGetSymbolAddress((void**)&pqh, g_qh);    cudaGetSymbolAddress((void**)&pkh, g_kh);
    cudaGetSymbolAddress((void**)&pvh, g_vh);
    cudaGetSymbolAddress((void**)&ph1, g_h1);    cudaGetSymbolAddress((void**)&pht1, g_ht1);
    cudaGetSymbolAddress((void**)&ph2, g_h2);    cudaGetSymbolAddress((void**)&phtkg, g_htkg);
    cudaGetSymbolAddress((void**)&pas1, g_as1);  cudaGetSymbolAddress((void**)&pad1, g_ad1);
    cudaGetSymbolAddress((void**)&pas2, g_as2);  cudaGetSymbolAddress((void**)&pad2, g_ad2);
    cudaGetSymbolAddress((void**)&pdinv, g_dinv);
    cudaGetSymbolAddress((void**)&pg1, g_g1);    cudaGetSymbolAddress((void**)&phe1, g_he1);
    cudaGetSymbolAddress((void**)&pg2, g_g2);    cudaGetSymbolAddress((void**)&phekg, g_hekg);
    cudaGetSymbolAddress((void**)&pq, g_q);      cudaGetSymbolAddress((void**)&pk, g_k);
    cudaGetSymbolAddress((void**)&pv, g_v);      cudaGetSymbolAddress((void**)&pao, g_attnout);
    cudaGetSymbolAddress((void**)&phat, g_hattn);
    cudaGetSymbolAddress((void**)&pt1, g_t1);
    cudaGetSymbolAddress((void**)&pqn, g_qn);    cudaGetSymbolAddress((void**)&pknm, g_knm);
    cudaGetSymbolAddress((void**)&pdsum, g_dsum);
    cudaGetSymbolAddress((void**)&pcnt_t, g_cnt_t); cudaGetSymbolAddress((void**)&pcur_t, g_cur_t);
    cudaGetSymbolAddress((void**)&poff_t, g_off_t); cudaGetSymbolAddress((void**)&psrcs_t, g_srcs_t);
    cudaGetSymbolAddress((void**)&pcnt_e, g_cnt_e); cudaGetSymbolAddress((void**)&pcur_e, g_cur_e);
    cudaGetSymbolAddress((void**)&poff_e, g_off_e); cudaGetSymbolAddress((void**)&psrcs_e, g_srcs_e);

    static cudaStream_t s1 = nullptr, s2 = nullptr;
    static cudaEvent_t evRoot = nullptr, evT = nullptr, evB = nullptr;
    if (!s1) {
        cudaStreamCreateWithFlags(&s1, cudaStreamNonBlocking);
        cudaStreamCreateWithFlags(&s2, cudaStreamNonBlocking);
        cudaEventCreateWithFlags(&evRoot, cudaEventDisableTiming);
        cudaEventCreateWithFlags(&evT, cudaEventDisableTiming);
        cudaEventCreateWithFlags(&evB, cudaEventDisableTiming);
    }

    const int T = 256;
    const int EB = (EE + T - 1) / T;

    // ===== fork =====
    cudaEventRecord(evRoot, 0);
    cudaStreamWaitEvent(s1, evRoot, 0);
    cudaStreamWaitEvent(s2, evRoot, 0);

    // ----- s1: CSR for TKG graph -----
    cudaMemsetAsync(pcnt_t, 0, NN * sizeof(int), s1);
    cudaMemsetAsync(pcur_t, 0, NN * sizeof(int), s1);
    hist_kernel<<<EB, T, 0, s1>>>(eit, pcnt_t);
    scan_kernel<<<1, 1024, 0, s1>>>(pcnt_t, poff_t);
    scatter_kernel<<<EB, T, 0, s1>>>(eit, poff_t, pcur_t, psrcs_t);
    cudaEventRecord(evT, s1);

    // ----- s2: CSR for EKG graph + full GCN branch + K/V projections -----
    cudaMemsetAsync(pcnt_e, 0, NN * sizeof(int), s2);
    cudaMemsetAsync(pcur_e, 0, NN * sizeof(int), s2);
    hist_kernel<<<EB, T, 0, s2>>>(eie, pcnt_e);
    scan_kernel<<<1, 1024, 0, s2>>>(pcnt_e, poff_e);
    scatter_kernel<<<EB, T, 0, s2>>>(eie, poff_e, pcur_e, psrcs_e);
    dinv_kernel<<<(NN + T - 1) / T, T, 0, s2>>>(pcnt_e, pdinv);
    gemm64<<<dim3(1, 128), 256, 0, s2>>>(x, nullptr, gcn1_W, nullptr, pg1, nullptr, NN, 64, DIN, 0);
    gcn_aggr_csr<<<(NN * 32 + T - 1) / T, T, 0, s2>>>(poff_e, psrcs_e, pg1, pdinv, gcn1_b, phe1);
    gemm64<<<dim3(1, 128), 256, 0, s2>>>(phe1, nullptr, gcn2_W, nullptr, pg2, nullptr, NN, 64, 64, 0);
    gcn_aggr_csr<<<(NN * 32 + T - 1) / T, T, 0, s2>>>(poff_e, psrcs_e, pg2, pdinv, gcn2_b, phekg);
    gemm64<<<dim3(1, 128), 256, 0, s2>>>(phekg, nullptr, Wk, bk, pk, pkh, NN, 64, 64, 0);
    gemm64<<<dim3(1, 128), 256, 0, s2>>>(phekg, nullptr, Wv, bv, pv, pvh, NN, 64, 64, 0);
    cudaEventRecord(evB, s2);

    // ----- s0: GAT branch (critical path) -----
    gemm64<<<dim3(2, 128), 256>>>(x, nullptr, gat1_W, nullptr, ph1, nullptr, NN, 128, DIN, 0);
    gat_alpha_coef<<<(NN * 2 + T - 1) / T, T>>>(ph1, gat1_as, gat1_ad, pas1, pad1, 2);
    cudaStreamWaitEvent(0, evT, 0);
    gat_aggr_csr<<<(NN * 2 * 32 + T - 1) / T, T>>>(poff_t, psrcs_t, pas1, pad1, ph1, gat1_b, pht1, 2);
    gemm64<<<dim3(1, 128), 256>>>(pht1, nullptr, gat2_W, nullptr, ph2, nullptr, NN, 64, 128, 0);
    gat_alpha_coef<<<(NN + T - 1) / T, T>>>(ph2, gat2_as, gat2_ad, pas2, pad2, 1);
    gat_aggr_csr<<<(NN * 32 + T - 1) / T, T>>>(poff_t, psrcs_t, pas2, pad2, ph2, gat2_b, phtkg, 1);
    gemm64<<<dim3(1, 128), 256>>>(phtkg, nullptr, Wq, bq, pq, pqh, NN, 64, 64, 0);
    cudaMemsetAsync(pknm, 0, 2 * sizeof(float));
    cudaMemsetAsync(pdsum, 0, NN * 2 * sizeof(float));
    cudaMemsetAsync(pao, 0, (size_t)NN * 64 * sizeof(float));
    cudaStreamWaitEvent(0, evB, 0);
    norms_kernel<<<(NN * 2 + T - 1) / T, T>>>(pq, pk, pqn, pknm);
    qk_exp_wmma<<<dim3(64, 128, 2), 256>>>(pqh, pkh, pqn, pknm, pS, pdsum);
    av_wmma<<<dim3(64, 4), 256>>>(pS, pvh, pdsum, pao, out_attn);
    gemm64<<<dim3(1, 128), 256>>>(pao, nullptr, Wo, bo, phat, nullptr, NN, 64, 64, 0);
    gemm64<<<dim3(1, 128), 256>>>(phtkg, phat, fc1_W, fc1_b, pt1, nullptr, NN, 64, 128, 1);
    fc2_kernel<<<(NN * 32 + T - 1) / T, T>>>(pt1, fc2_W, fc2_b, out_pred);
}